// round 1
// baseline (speedup 1.0000x reference)
#include <cuda_runtime.h>
#include <cuda_bf16.h>
#include <cstdint>

// Problem constants
#define BC      16            // B*C = 8*2
#define LL      2048          // sequence length
#define TSZ     17            // filter size
#define PAD     8             // TSZ/2
#define XPLEN   2080          // padded row: 2048+16 valid, padded to mult of 32
#define TSTRIDE 20            // xf row stride (17 padded to 20 for float4 loads)

// Scratch (device globals -- no allocations allowed)
__device__ float g_xp[BC * XPLEN];            // zero-padded x
__device__ float g_xf[BC * LL * TSTRIDE];     // xf[bc][l][t]

// ---------------- f32x2 helpers (sm_103a packed fp32) ----------------
typedef double f32x2;

__device__ __forceinline__ f32x2 pack2(float lo, float hi) {
    f32x2 r;
    asm("mov.b64 %0, {%1, %2};" : "=d"(r) : "f"(lo), "f"(hi));
    return r;
}
__device__ __forceinline__ void ffma2(f32x2& d, f32x2 a, f32x2 b) {
    asm("fma.rn.f32x2 %0, %1, %2, %0;" : "+d"(d) : "d"(a), "d"(b));
}
__device__ __forceinline__ void unpack2(f32x2 v, float& lo, float& hi) {
    asm("mov.b64 {%0, %1}, %2;" : "=f"(lo), "=f"(hi) : "d"(v));
}

// ---------------- Kernel 0: build padded x ----------------
__global__ void build_xp_kernel(const float* __restrict__ x) {
    int i = blockIdx.x * blockDim.x + threadIdx.x;
    if (i >= BC * XPLEN) return;
    int bc = i / XPLEN;
    int p  = i - bc * XPLEN;
    float v = 0.0f;
    int l = p - PAD;
    if (l >= 0 && l < LL) v = x[bc * LL + l];
    g_xp[i] = v;
}

// ---------------- Kernel 1: xf[bc][l][t] = sum_s xp[bc][l+s] * filt[c][s][t] ----------------
__global__ void build_xf_kernel(const float* __restrict__ filt) {
    __shared__ float sf[TSZ * TSZ];
    int row = blockIdx.x * 256 + threadIdx.x;   // 0 .. BC*LL-1 (256 divides 2048 -> one bc per block)
    int bc = row >> 11;
    int l  = row & (LL - 1);
    int c  = bc & 1;

    for (int i = threadIdx.x; i < TSZ * TSZ; i += 256)
        sf[i] = filt[c * TSZ * TSZ + i];
    __syncthreads();

    float acc[TSZ];
#pragma unroll
    for (int t = 0; t < TSZ; t++) acc[t] = 0.0f;

    const float* xr = g_xp + bc * XPLEN + l;    // xs[l,s] = xp[l+s]
#pragma unroll
    for (int s = 0; s < TSZ; s++) {
        float xv = xr[s];
#pragma unroll
        for (int t = 0; t < TSZ; t++)
            acc[t] += xv * sf[s * TSZ + t];
    }

    float* o = g_xf + (size_t)(bc * LL + l) * TSTRIDE;
#pragma unroll
    for (int t = 0; t < TSZ; t++) o[t] = acc[t];
    o[17] = 0.0f; o[18] = 0.0f; o[19] = 0.0f;
}

// ---------------- Kernel 2: main outer product ----------------
// out[bc][l][m] = sum_t xf[bc][l][t] * xp[bc][m+t]
// CTA tile: 64 (l) x 128 (m), 256 threads = 16 (l-groups) x 16 (m-groups)
// thread tile: RL=4 rows x RM=8 cols  (4 f32x2 per row)
#define TL 64
#define TM 128
#define RL 4
#define RM 8

__global__ void __launch_bounds__(256)
filter_main_kernel(float* __restrict__ out) {
    const int bc = blockIdx.z;
    const int l0 = blockIdx.y * TL;
    const int m0 = blockIdx.x * TM;
    const int tx = threadIdx.x & 15;   // m group
    const int ty = threadIdx.x >> 4;   // l group
    const int mg = m0 + tx * RM;       // multiple of 8 -> 32B aligned
    const int lg = l0 + ty * RL;

    // ---- load 24 x values for this thread's m-window, pack into 23 pairs ----
    const float4* xp4 = reinterpret_cast<const float4*>(g_xp + bc * XPLEN + mg);
    float xv[24];
#pragma unroll
    for (int q = 0; q < 6; q++) {
        float4 v = xp4[q];
        xv[4 * q + 0] = v.x; xv[4 * q + 1] = v.y;
        xv[4 * q + 2] = v.z; xv[4 * q + 3] = v.w;
    }
    f32x2 bp[23];
#pragma unroll
    for (int k = 0; k < 23; k++) bp[k] = pack2(xv[k], xv[k + 1]);

    // ---- load xf rows (4 rows x 20 via float4) ----
    float a[RL][TSTRIDE];
#pragma unroll
    for (int r = 0; r < RL; r++) {
        const float4* ar = reinterpret_cast<const float4*>(
            g_xf + (size_t)(bc * LL + lg + r) * TSTRIDE);
#pragma unroll
        for (int q = 0; q < 5; q++) {
            float4 v = ar[q];
            a[r][4 * q + 0] = v.x; a[r][4 * q + 1] = v.y;
            a[r][4 * q + 2] = v.z; a[r][4 * q + 3] = v.w;
        }
    }

    // ---- accumulate: 4 rows x 4 f32x2 pairs, 17 taps ----
    f32x2 acc[RL][4];
#pragma unroll
    for (int r = 0; r < RL; r++)
#pragma unroll
        for (int j = 0; j < 4; j++) acc[r][j] = 0.0;   // bitpattern = {+0.f,+0.f}

#pragma unroll
    for (int t = 0; t < TSZ; t++) {
#pragma unroll
        for (int r = 0; r < RL; r++) {
            f32x2 ap = pack2(a[r][t], a[r][t]);
#pragma unroll
            for (int j = 0; j < 4; j++)
                ffma2(acc[r][j], ap, bp[t + 2 * j]);
        }
    }

    // ---- store: 2x float4 per row, fully coalesced ----
#pragma unroll
    for (int r = 0; r < RL; r++) {
        float o[8];
#pragma unroll
        for (int j = 0; j < 4; j++) unpack2(acc[r][j], o[2 * j], o[2 * j + 1]);
        float4* orow = reinterpret_cast<float4*>(
            out + (size_t)(bc * LL + lg + r) * LL + mg);
        orow[0] = make_float4(o[0], o[1], o[2], o[3]);
        orow[1] = make_float4(o[4], o[5], o[6], o[7]);
    }
}

extern "C" void kernel_launch(void* const* d_in, const int* in_sizes, int n_in,
                              void* d_out, int out_size) {
    const float* x    = (const float*)d_in[0];   // [8,2,2048]
    const float* filt = (const float*)d_in[1];   // [1,2,17,17]
    float* out = (float*)d_out;                  // [8,2,2048,2048]

    {
        int n = BC * XPLEN;
        build_xp_kernel<<<(n + 255) / 256, 256>>>(x);
    }
    {
        int n = BC * LL;
        build_xf_kernel<<<n / 256, 256>>>(filt);
    }
    {
        dim3 grid(LL / TM, LL / TL, BC);
        filter_main_kernel<<<grid, 256>>>(out);
    }
}